// round 2
// baseline (speedup 1.0000x reference)
#include <cuda_runtime.h>
#include <cuda_bf16.h>
#include <cstdint>

#define HDIM 1024
#define ADIM 1024
#define EDIM 1024
#define SDIM 2048
#define VDIM 50257
#define NBOUND 25
#define MERGED (HDIM + ADIM)   // 2048

// ---------------- device scratch (no allocation allowed) ----------------
__device__ __align__(16) float g_h[2][HDIM];
__device__ __align__(16) float g_q[ADIM];
__device__ __align__(16) float g_s[SDIM];
__device__ __align__(16) float g_w[SDIM];
__device__ __align__(16) float g_ctx_part[8][ADIM];
__device__ __align__(16) float g_merge[MERGED];
__device__ __align__(16) float g_eproj[(size_t)SDIM * ADIM];          // 8 MB
__device__ __align__(16) __nv_bfloat16 g_wbf[(size_t)VDIM * MERGED];  // 206 MB bf16 W_out
__device__ __align__(16) float g_ub[VDIM];                            // per-row logit upper bound
__device__ int g_word;
__device__ unsigned g_M;        // encoded max lower-bound (atomicMax)
__device__ int g_ctr_s, g_ctr_c, g_ctr_v;   // last-block counters

// ---------------- helpers ----------------
__device__ __forceinline__ float warp_sum(float v) {
#pragma unroll
    for (int o = 16; o; o >>= 1) v += __shfl_xor_sync(0xffffffffu, v, o);
    return v;
}
// order-preserving float<->uint encode for atomicMax over signed floats
__device__ __forceinline__ unsigned enc_f(float f) {
    unsigned b = __float_as_uint(f);
    return (b & 0x80000000u) ? ~b : (b | 0x80000000u);
}
__device__ __forceinline__ float dec_f(unsigned u) {
    unsigned b = (u & 0x80000000u) ? (u ^ 0x80000000u) : ~u;
    return __uint_as_float(b);
}
// FFMA-only 2^y (rel err ~1e-7)
__device__ __forceinline__ float exp2_fast(float y) {
    y = fminf(fmaxf(y, -60.f), 60.f);
    float n = rintf(y);
    float f = y - n;
    float p = 1.5403530e-4f;
    p = fmaf(p, f, 1.3333558e-3f);
    p = fmaf(p, f, 9.6181291e-3f);
    p = fmaf(p, f, 5.5504109e-2f);
    p = fmaf(p, f, 2.4022651e-1f);
    p = fmaf(p, f, 6.9314718e-1f);
    p = fmaf(p, f, 1.0f);
    return __int_as_float(((int)n + 127) << 23) * p;
}
__device__ __forceinline__ float tanh_fast(float x) {
    float e = exp2_fast(x * 2.885390081777927f);
    return 1.f - 2.f / (e + 1.f);
}
__device__ __forceinline__ float sigmoid_fast(float x) {
    float e = exp2_fast(-1.4426950408889634f * x);
    return 1.f / (1.f + e);
}

// ---------------- kernels ----------------
__global__ void k_init(const float* __restrict__ hidden) {
    for (int i = threadIdx.x; i < HDIM; i += blockDim.x) g_h[0][i] = hidden[i];
    if (threadIdx.x == 0) {
        g_word = 1;  // SOS
        g_M = 0u;
        g_ctr_s = 0; g_ctr_c = 0; g_ctr_v = 0;
    }
}

// one-time fp32 -> bf16 conversion of W_out
__global__ void k_quant(const float* __restrict__ W) {
    size_t idx = (size_t)blockIdx.x * 512 + threadIdx.x;     // handles 8 elems
    size_t n8 = (size_t)VDIM * MERGED / 8;
    if (idx < n8) {
        const float4* p = (const float4*)W + idx * 2;
        float4 a = __ldcs(p);
        float4 b = __ldcs(p + 1);
        uint4 o;
        *(__nv_bfloat162*)&o.x = __nv_bfloat162(__float2bfloat16(a.x), __float2bfloat16(a.y));
        *(__nv_bfloat162*)&o.y = __nv_bfloat162(__float2bfloat16(a.z), __float2bfloat16(a.w));
        *(__nv_bfloat162*)&o.z = __nv_bfloat162(__float2bfloat16(b.x), __float2bfloat16(b.y));
        *(__nv_bfloat162*)&o.w = __nv_bfloat162(__float2bfloat16(b.z), __float2bfloat16(b.w));
        ((uint4*)g_wbf)[idx] = o;
    }
}

// eproj[s,a] = sum_k emb[s,k] * W_e[a,k] + b_a[a]
__global__ void k_eproj(const float* __restrict__ emb, const float* __restrict__ We,
                        const float* __restrict__ ba) {
    __shared__ float As[32][33];
    __shared__ float Bs[32][33];
    int tx = threadIdx.x, ty = threadIdx.y;
    int srow = blockIdx.x * 32 + ty;
    int arow = blockIdx.y * 32 + ty;
    float acc = 0.f;
    for (int kt = 0; kt < EDIM; kt += 32) {
        As[ty][tx] = emb[(size_t)srow * EDIM + kt + tx];
        Bs[ty][tx] = We[(size_t)arow * EDIM + kt + tx];
        __syncthreads();
#pragma unroll
        for (int k = 0; k < 32; k++) acc = fmaf(As[ty][k], Bs[tx][k], acc);
        __syncthreads();
    }
    int a = blockIdx.y * 32 + tx;
    g_eproj[(size_t)srow * ADIM + a] = acc + ba[a];
}

// GRU: one block per hidden unit j, 6 warps = 6 dot products
__global__ void k_gru(const float* __restrict__ emb_table,
                      const float* __restrict__ W_ih, const float* __restrict__ W_hh,
                      const float* __restrict__ b_ih, const float* __restrict__ b_hh,
                      int pold) {
    int j = blockIdx.x;
    int w = threadIdx.x >> 5, lane = threadIdx.x & 31;
    __shared__ float dots[6];
    int word = g_word;
    const float* vec = (w < 3) ? (emb_table + (size_t)word * EDIM) : g_h[pold];
    const float* mat = (w < 3) ? (W_ih + (size_t)(w * HDIM + j) * EDIM)
                               : (W_hh + (size_t)((w - 3) * HDIM + j) * HDIM);
    const float4* m4 = (const float4*)mat;
    const float4* v4 = (const float4*)vec;
    float acc = 0.f;
#pragma unroll
    for (int i = 0; i < 8; i++) {
        float4 a = m4[lane + 32 * i];
        float4 b = v4[lane + 32 * i];
        acc = fmaf(a.x, b.x, acc); acc = fmaf(a.y, b.y, acc);
        acc = fmaf(a.z, b.z, acc); acc = fmaf(a.w, b.w, acc);
    }
    acc = warp_sum(acc);
    if (lane == 0) {
        float bia = (w < 3) ? b_ih[w * HDIM + j] : b_hh[(w - 3) * HDIM + j];
        dots[w] = acc + bia;
    }
    __syncthreads();
    if (threadIdx.x == 0) {
        float r = sigmoid_fast(dots[0] + dots[3]);
        float z = sigmoid_fast(dots[1] + dots[4]);
        float n = tanh_fast(dots[2] + r * dots[5]);
        float hold = g_h[pold][j];
        g_h[pold ^ 1][j] = (1.f - z) * n + z * hold;
    }
}

// q[a] = h_new . W_q[a,:]  — one block per row for latency hiding
__global__ void k_q(const float* __restrict__ Wq, int pnew) {
    int a = blockIdx.x;
    int w = threadIdx.x >> 5, lane = threadIdx.x & 31;
    __shared__ float red[4];
    const float4* m4 = (const float4*)(Wq + (size_t)a * HDIM);
    const float4* v4 = (const float4*)g_h[pnew];
    float acc = 0.f;
#pragma unroll
    for (int i = 0; i < 2; i++) {
        int k = threadIdx.x + 128 * i;
        float4 mm = m4[k];
        float4 vv = __ldg(v4 + k);
        acc = fmaf(mm.x, vv.x, acc); acc = fmaf(mm.y, vv.y, acc);
        acc = fmaf(mm.z, vv.z, acc); acc = fmaf(mm.w, vv.w, acc);
    }
    acc = warp_sum(acc);
    if (lane == 0) red[w] = acc;
    __syncthreads();
    if (threadIdx.x == 0) g_q[a] = red[0] + red[1] + red[2] + red[3];
}

// s[j] = sum_a tanh(eproj[j,a] + q[a]) * v_a[a]; last block runs softmax + writes weights
__global__ void k_s(const float* __restrict__ va, float* __restrict__ out, int t) {
    __shared__ __align__(16) float qs[ADIM];
    __shared__ __align__(16) float vs[ADIM];
    __shared__ float red[8];
    __shared__ int is_last;
    for (int i = threadIdx.x; i < ADIM; i += 256) { qs[i] = g_q[i]; vs[i] = va[i]; }
    __syncthreads();
    int w = threadIdx.x >> 5, lane = threadIdx.x & 31;
    int j = blockIdx.x * 8 + w;
    const float4* ep4 = (const float4*)(g_eproj + (size_t)j * ADIM);
    const float4* q4 = (const float4*)qs;
    const float4* v4 = (const float4*)vs;
    float acc = 0.f;
#pragma unroll
    for (int i = 0; i < 8; i++) {
        int k = lane + 32 * i;
        float4 e = ep4[k]; float4 q = q4[k]; float4 v = v4[k];
        acc = fmaf(tanh_fast(e.x + q.x), v.x, acc);
        acc = fmaf(tanh_fast(e.y + q.y), v.y, acc);
        acc = fmaf(tanh_fast(e.z + q.z), v.z, acc);
        acc = fmaf(tanh_fast(e.w + q.w), v.w, acc);
    }
    acc = warp_sum(acc);
    if (lane == 0) g_s[j] = acc;

    // ---- last block: softmax over 2048 ----
    __threadfence();
    if (threadIdx.x == 0) {
        int c = atomicAdd(&g_ctr_s, 1);
        is_last = (c == (int)gridDim.x - 1);
        if (is_last) g_ctr_s = 0;
    }
    __syncthreads();
    if (!is_last) return;

    float v8[8];
    float m = -3.4e38f;
#pragma unroll
    for (int k = 0; k < 8; k++) {
        v8[k] = g_s[threadIdx.x + 256 * k];
        m = fmaxf(m, v8[k]);
    }
#pragma unroll
    for (int o = 16; o; o >>= 1) m = fmaxf(m, __shfl_xor_sync(0xffffffffu, m, o));
    if (lane == 0) red[w] = m;
    __syncthreads();
    m = red[0];
#pragma unroll
    for (int k = 1; k < 8; k++) m = fmaxf(m, red[k]);
    float ssum = 0.f;
#pragma unroll
    for (int k = 0; k < 8; k++) { v8[k] = expf(v8[k] - m); ssum += v8[k]; }
    ssum = warp_sum(ssum);
    __syncthreads();
    if (lane == 0) red[w] = ssum;
    __syncthreads();
    float tot = red[0];
#pragma unroll
    for (int k = 1; k < 8; k++) tot += red[k];
    float inv = 1.f / tot;
    size_t base = (size_t)NBOUND + (size_t)t * SDIM;
#pragma unroll
    for (int k = 0; k < 8; k++) {
        float wv = v8[k] * inv;
        g_w[threadIdx.x + 256 * k] = wv;
        out[base + threadIdx.x + 256 * k] = wv;
    }
}

// ctx partials; last block reduces partials + builds merge vector
__global__ void k_ctx(const float* __restrict__ e, int pnew) {
    __shared__ float ws[256];
    __shared__ int is_last;
    int s0 = blockIdx.y * 256;
    ws[threadIdx.x] = g_w[s0 + threadIdx.x];
    __syncthreads();
    int a = blockIdx.x * 256 + threadIdx.x;
    float acc = 0.f;
#pragma unroll 4
    for (int s = 0; s < 256; s++)
        acc = fmaf(ws[s], e[(size_t)(s0 + s) * ADIM + a], acc);
    g_ctx_part[blockIdx.y][a] = acc;

    __threadfence();
    if (threadIdx.x == 0) {
        int c = atomicAdd(&g_ctr_c, 1);
        is_last = (c == (int)(gridDim.x * gridDim.y) - 1);
        if (is_last) g_ctr_c = 0;
    }
    __syncthreads();
    if (!is_last) return;
    for (int i = threadIdx.x; i < ADIM; i += 256) {
        g_merge[i] = g_h[pnew][i];
        float cc = 0.f;
#pragma unroll
        for (int p = 0; p < 8; p++) cc += g_ctx_part[p][i];
        g_merge[HDIM + i] = cc;
    }
}

// bf16 vocab GEMV with exact-bound; last block rescores margin candidates in fp32 + decodes
__global__ void k_vocab(const float* __restrict__ Wout, const float* __restrict__ bout,
                        float* __restrict__ out, int t) {
    __shared__ __align__(16) float ms[MERGED];
    __shared__ float red[16];
    __shared__ int is_last;
    ((float4*)ms)[threadIdx.x] = ((const float4*)g_merge)[threadIdx.x];
    __syncthreads();
    int w = threadIdx.x >> 5, lane = threadIdx.x & 31;
    int v = blockIdx.x * 16 + w;
    if (v < VDIM) {
        const uint2* r2 = (const uint2*)(g_wbf + (size_t)v * MERGED);
        const float4* m4 = (const float4*)ms;
        float acc = 0.f, ab = 0.f;
#pragma unroll
        for (int i = 0; i < 16; i++) {
            uint2 u = __ldcs(r2 + lane + 32 * i);
            float4 m = m4[lane + 32 * i];
            float2 f0 = __bfloat1622float2(*(__nv_bfloat162*)&u.x);
            float2 f1 = __bfloat1622float2(*(__nv_bfloat162*)&u.y);
            acc = fmaf(f0.x, m.x, acc); ab = fmaf(fabsf(f0.x), fabsf(m.x), ab);
            acc = fmaf(f0.y, m.y, acc); ab = fmaf(fabsf(f0.y), fabsf(m.y), ab);
            acc = fmaf(f1.x, m.z, acc); ab = fmaf(fabsf(f1.x), fabsf(m.z), ab);
            acc = fmaf(f1.y, m.w, acc); ab = fmaf(fabsf(f1.y), fabsf(m.w), ab);
        }
        acc = warp_sum(acc);
        ab = warp_sum(ab);
        if (lane == 0) {
            float A = acc + bout[v];
            float B = fmaf(ab, 0.00390625f, 1e-4f);   // 2^-8 bf16 half-ulp bound + slack
            g_ub[v] = A + B;
            atomicMax(&g_M, enc_f(A - B));
        }
    }

    // ---- last block: exact rescore of candidates + decode ----
    __threadfence();
    if (threadIdx.x == 0) {
        int c = atomicAdd(&g_ctr_v, 1);
        is_last = (c == (int)gridDim.x - 1);
        if (is_last) g_ctr_v = 0;
    }
    __syncthreads();
    if (!is_last) return;

    float thr = dec_f(g_M);
    __shared__ int s_cand[512];
    __shared__ int s_n;
    __shared__ float s_bl;
    __shared__ int s_bi;
    if (threadIdx.x == 0) { s_bl = -3.4e38f; s_bi = 0; }
    for (int base = 0; base < VDIM; base += 512) {
        if (threadIdx.x == 0) s_n = 0;
        __syncthreads();
        int i = base + threadIdx.x;
        if (i < VDIM && g_ub[i] >= thr) {
            int p = atomicAdd(&s_n, 1);
            s_cand[p] = i;
        }
        __syncthreads();
        int n = s_n;
        for (int c = 0; c < n; c++) {
            int vv = s_cand[c];
            const float4* r4 = (const float4*)(Wout + (size_t)vv * MERGED);
            float4 rr = __ldg(r4 + threadIdx.x);
            float4 mm = ((float4*)ms)[threadIdx.x];
            float a = fmaf(rr.x, mm.x, fmaf(rr.y, mm.y, fmaf(rr.z, mm.z, rr.w * mm.w)));
            a = warp_sum(a);
            if (lane == 0) red[w] = a;
            __syncthreads();
            if (threadIdx.x == 0) {
                float L = 0.f;
#pragma unroll
                for (int k = 0; k < 16; k++) L += red[k];
                L += bout[vv];
                if (L > s_bl || (L == s_bl && vv < s_bi)) { s_bl = L; s_bi = vv; }
            }
            __syncthreads();
        }
        __syncthreads();
    }
    if (threadIdx.x == 0) {
        g_word = s_bi;
        out[t] = (float)s_bi;
        g_M = 0u;   // reset for next step
    }
}

// ---------------- launch ----------------
extern "C" void kernel_launch(void* const* d_in, const int* in_sizes, int n_in,
                              void* d_out, int out_size) {
    const float* hidden     = (const float*)d_in[0];
    const float* embeddings = (const float*)d_in[1];
    const float* emb_table  = (const float*)d_in[2];
    const float* W_ih       = (const float*)d_in[3];
    const float* W_hh       = (const float*)d_in[4];
    const float* b_ih       = (const float*)d_in[5];
    const float* b_hh       = (const float*)d_in[6];
    const float* W_e        = (const float*)d_in[7];
    const float* W_q        = (const float*)d_in[8];
    const float* b_a        = (const float*)d_in[9];
    const float* v_a        = (const float*)d_in[10];
    const float* W_out      = (const float*)d_in[11];
    const float* b_out      = (const float*)d_in[12];
    float* out = (float*)d_out;

    k_init<<<1, 256>>>(hidden);
    {
        size_t n8 = (size_t)VDIM * MERGED / 8;
        int blocks = (int)((n8 + 511) / 512);
        k_quant<<<blocks, 512>>>(W_out);
    }
    k_eproj<<<dim3(SDIM / 32, ADIM / 32), dim3(32, 32)>>>(embeddings, W_e, b_a);

    for (int t = 0; t < NBOUND; t++) {
        int pold = t & 1;
        int pnew = pold ^ 1;
        k_gru<<<1024, 192>>>(emb_table, W_ih, W_hh, b_ih, b_hh, pold);
        k_q<<<1024, 128>>>(W_q, pnew);
        k_s<<<256, 256>>>(v_a, out, t);
        k_ctx<<<dim3(4, 8), 256>>>(embeddings, pnew);
        k_vocab<<<(VDIM + 15) / 16, 512>>>(W_out, b_out, out, t);
    }
}

// round 3
// speedup vs baseline: 1.3108x; 1.3108x over previous
#include <cuda_runtime.h>
#include <cuda_bf16.h>
#include <cstdint>

#define HDIM 1024
#define ADIM 1024
#define EDIM 1024
#define SDIM 2048
#define VDIM 50257
#define NBOUND 25
#define MERGED (HDIM + ADIM)   // 2048
#define VPAD 50260             // VDIM padded to multiple of 4

// ---------------- device scratch (no allocation allowed) ----------------
__device__ __align__(16) float g_h[2][HDIM];
__device__ __align__(16) float g_q[ADIM];
__device__ __align__(16) float g_s[SDIM];
__device__ __align__(16) float g_w[SDIM];
__device__ __align__(16) float g_ctx_part[8][ADIM];
__device__ __align__(16) float g_merge[MERGED];
__device__ __align__(16) float g_eproj[(size_t)SDIM * ADIM];          // 8 MB
__device__ __align__(16) __nv_bfloat16 g_wbf[(size_t)VDIM * MERGED];  // 206 MB bf16 W_out
__device__ __align__(16) float g_ub[VPAD];                            // per-row logit upper bound
__device__ int g_word;
__device__ unsigned g_M;        // encoded max lower-bound (atomicMax)
__device__ int g_ctr_s, g_ctr_c, g_ctr_v;   // last-block counters

// ---------------- helpers ----------------
__device__ __forceinline__ float warp_sum(float v) {
#pragma unroll
    for (int o = 16; o; o >>= 1) v += __shfl_xor_sync(0xffffffffu, v, o);
    return v;
}
// order-preserving float<->uint encode for atomicMax over signed floats
__device__ __forceinline__ unsigned enc_f(float f) {
    unsigned b = __float_as_uint(f);
    return (b & 0x80000000u) ? ~b : (b | 0x80000000u);
}
__device__ __forceinline__ float dec_f(unsigned u) {
    unsigned b = (u & 0x80000000u) ? (u ^ 0x80000000u) : ~u;
    return __uint_as_float(b);
}
// FFMA-only 2^y (rel err ~1e-7)
__device__ __forceinline__ float exp2_fast(float y) {
    y = fminf(fmaxf(y, -60.f), 60.f);
    float n = rintf(y);
    float f = y - n;
    float p = 1.5403530e-4f;
    p = fmaf(p, f, 1.3333558e-3f);
    p = fmaf(p, f, 9.6181291e-3f);
    p = fmaf(p, f, 5.5504109e-2f);
    p = fmaf(p, f, 2.4022651e-1f);
    p = fmaf(p, f, 6.9314718e-1f);
    p = fmaf(p, f, 1.0f);
    return __int_as_float(((int)n + 127) << 23) * p;
}
__device__ __forceinline__ float tanh_fast(float x) {
    float e = exp2_fast(x * 2.885390081777927f);
    return 1.f - 2.f / (e + 1.f);
}
__device__ __forceinline__ float sigmoid_fast(float x) {
    float e = exp2_fast(-1.4426950408889634f * x);
    return 1.f / (1.f + e);
}

// ---------------- kernels ----------------
__global__ void k_init(const float* __restrict__ hidden) {
    for (int i = threadIdx.x; i < HDIM; i += blockDim.x) g_h[0][i] = hidden[i];
    if (threadIdx.x == 0) {
        g_word = 1;  // SOS
        g_M = 0u;
        g_ctr_s = 0; g_ctr_c = 0; g_ctr_v = 0;
        for (int i = VDIM; i < VPAD; i++) g_ub[i] = -3.4e38f;  // pad never selected
    }
}

// one-time fp32 -> bf16 conversion of W_out (streaming loads AND stores: keep L2 clean)
__global__ void k_quant(const float* __restrict__ W) {
    size_t idx = (size_t)blockIdx.x * 512 + threadIdx.x;     // handles 8 elems
    size_t n8 = (size_t)VDIM * MERGED / 8;
    if (idx < n8) {
        const float4* p = (const float4*)W + idx * 2;
        float4 a = __ldcs(p);
        float4 b = __ldcs(p + 1);
        uint4 o;
        *(__nv_bfloat162*)&o.x = __nv_bfloat162(__float2bfloat16(a.x), __float2bfloat16(a.y));
        *(__nv_bfloat162*)&o.y = __nv_bfloat162(__float2bfloat16(a.z), __float2bfloat16(a.w));
        *(__nv_bfloat162*)&o.z = __nv_bfloat162(__float2bfloat16(b.x), __float2bfloat16(b.y));
        *(__nv_bfloat162*)&o.w = __nv_bfloat162(__float2bfloat16(b.z), __float2bfloat16(b.w));
        __stcs((uint4*)g_wbf + idx, o);
    }
}

// eproj[s,a] = sum_k emb[s,k] * W_e[a,k] + b_a[a]
__global__ void k_eproj(const float* __restrict__ emb, const float* __restrict__ We,
                        const float* __restrict__ ba) {
    __shared__ float As[32][33];
    __shared__ float Bs[32][33];
    int tx = threadIdx.x, ty = threadIdx.y;
    int srow = blockIdx.x * 32 + ty;
    int arow = blockIdx.y * 32 + ty;
    float acc = 0.f;
    for (int kt = 0; kt < EDIM; kt += 32) {
        As[ty][tx] = emb[(size_t)srow * EDIM + kt + tx];
        Bs[ty][tx] = We[(size_t)arow * EDIM + kt + tx];
        __syncthreads();
#pragma unroll
        for (int k = 0; k < 32; k++) acc = fmaf(As[ty][k], Bs[tx][k], acc);
        __syncthreads();
    }
    int a = blockIdx.y * 32 + tx;
    g_eproj[(size_t)srow * ADIM + a] = acc + ba[a];
}

// GRU: 2 hidden units per block, 12 warps = 12 dot products
__global__ void k_gru(const float* __restrict__ emb_table,
                      const float* __restrict__ W_ih, const float* __restrict__ W_hh,
                      const float* __restrict__ b_ih, const float* __restrict__ b_hh,
                      int pold) {
    int w = threadIdx.x >> 5, lane = threadIdx.x & 31;
    int sub = w % 6;                  // which of the 6 dot products
    int jj = w / 6;                   // 0 or 1
    int j = blockIdx.x * 2 + jj;
    __shared__ float dots[2][6];
    int word = g_word;
    const float* vec = (sub < 3) ? (emb_table + (size_t)word * EDIM) : g_h[pold];
    const float* mat = (sub < 3) ? (W_ih + (size_t)(sub * HDIM + j) * EDIM)
                                 : (W_hh + (size_t)((sub - 3) * HDIM + j) * HDIM);
    const float4* m4 = (const float4*)mat;
    const float4* v4 = (const float4*)vec;
    float acc = 0.f;
#pragma unroll
    for (int i = 0; i < 8; i++) {
        float4 a = m4[lane + 32 * i];
        float4 b = __ldg(v4 + lane + 32 * i);
        acc = fmaf(a.x, b.x, acc); acc = fmaf(a.y, b.y, acc);
        acc = fmaf(a.z, b.z, acc); acc = fmaf(a.w, b.w, acc);
    }
    acc = warp_sum(acc);
    if (lane == 0) {
        float bia = (sub < 3) ? b_ih[sub * HDIM + j] : b_hh[(sub - 3) * HDIM + j];
        dots[jj][sub] = acc + bia;
    }
    __syncthreads();
    if (threadIdx.x < 2) {
        int jo = blockIdx.x * 2 + threadIdx.x;
        float* d = dots[threadIdx.x];
        float r = sigmoid_fast(d[0] + d[3]);
        float z = sigmoid_fast(d[1] + d[4]);
        float n = tanh_fast(d[2] + r * d[5]);
        float hold = g_h[pold][jo];
        g_h[pold ^ 1][jo] = (1.f - z) * n + z * hold;
    }
}

// q[a] = h_new . W_q[a,:]  — one block per row
__global__ void k_q(const float* __restrict__ Wq, int pnew) {
    int a = blockIdx.x;
    int w = threadIdx.x >> 5, lane = threadIdx.x & 31;
    __shared__ float red[4];
    const float4* m4 = (const float4*)(Wq + (size_t)a * HDIM);
    const float4* v4 = (const float4*)g_h[pnew];
    float acc = 0.f;
#pragma unroll
    for (int i = 0; i < 2; i++) {
        int k = threadIdx.x + 128 * i;
        float4 mm = m4[k];
        float4 vv = __ldg(v4 + k);
        acc = fmaf(mm.x, vv.x, acc); acc = fmaf(mm.y, vv.y, acc);
        acc = fmaf(mm.z, vv.z, acc); acc = fmaf(mm.w, vv.w, acc);
    }
    acc = warp_sum(acc);
    if (lane == 0) red[w] = acc;
    __syncthreads();
    if (threadIdx.x == 0) g_q[a] = red[0] + red[1] + red[2] + red[3];
}

// s[j] = sum_a tanh(eproj[j,a] + q[a]) * v_a[a]; last block runs softmax + writes weights
__global__ void k_s(const float* __restrict__ va, float* __restrict__ out, int t) {
    __shared__ __align__(16) float qs[ADIM];
    __shared__ __align__(16) float vs[ADIM];
    __shared__ float red[8];
    __shared__ int is_last;
    for (int i = threadIdx.x; i < ADIM; i += 256) { qs[i] = g_q[i]; vs[i] = va[i]; }
    __syncthreads();
    int w = threadIdx.x >> 5, lane = threadIdx.x & 31;
    int j = blockIdx.x * 8 + w;
    const float4* ep4 = (const float4*)(g_eproj + (size_t)j * ADIM);
    const float4* q4 = (const float4*)qs;
    const float4* v4 = (const float4*)vs;
    float acc = 0.f;
#pragma unroll
    for (int i = 0; i < 8; i++) {
        int k = lane + 32 * i;
        float4 e = ep4[k]; float4 q = q4[k]; float4 v = v4[k];
        acc = fmaf(tanh_fast(e.x + q.x), v.x, acc);
        acc = fmaf(tanh_fast(e.y + q.y), v.y, acc);
        acc = fmaf(tanh_fast(e.z + q.z), v.z, acc);
        acc = fmaf(tanh_fast(e.w + q.w), v.w, acc);
    }
    acc = warp_sum(acc);
    if (lane == 0) g_s[j] = acc;

    // ---- last block: softmax over 2048 ----
    __threadfence();
    if (threadIdx.x == 0) {
        int c = atomicAdd(&g_ctr_s, 1);
        is_last = (c == (int)gridDim.x - 1);
        if (is_last) g_ctr_s = 0;
    }
    __syncthreads();
    if (!is_last) return;

    float v8[8];
    float m = -3.4e38f;
#pragma unroll
    for (int k = 0; k < 8; k++) {
        v8[k] = g_s[threadIdx.x + 256 * k];
        m = fmaxf(m, v8[k]);
    }
#pragma unroll
    for (int o = 16; o; o >>= 1) m = fmaxf(m, __shfl_xor_sync(0xffffffffu, m, o));
    if (lane == 0) red[w] = m;
    __syncthreads();
    m = red[0];
#pragma unroll
    for (int k = 1; k < 8; k++) m = fmaxf(m, red[k]);
    float ssum = 0.f;
#pragma unroll
    for (int k = 0; k < 8; k++) { v8[k] = expf(v8[k] - m); ssum += v8[k]; }
    ssum = warp_sum(ssum);
    __syncthreads();
    if (lane == 0) red[w] = ssum;
    __syncthreads();
    float tot = red[0];
#pragma unroll
    for (int k = 1; k < 8; k++) tot += red[k];
    float inv = 1.f / tot;
    size_t base = (size_t)NBOUND + (size_t)t * SDIM;
#pragma unroll
    for (int k = 0; k < 8; k++) {
        float wv = v8[k] * inv;
        g_w[threadIdx.x + 256 * k] = wv;
        out[base + threadIdx.x + 256 * k] = wv;
    }
}

// ctx partials; last block reduces partials + builds merge vector
__global__ void k_ctx(const float* __restrict__ e, int pnew) {
    __shared__ float ws[256];
    __shared__ int is_last;
    int s0 = blockIdx.y * 256;
    ws[threadIdx.x] = g_w[s0 + threadIdx.x];
    __syncthreads();
    int a = blockIdx.x * 256 + threadIdx.x;
    float acc = 0.f;
#pragma unroll 4
    for (int s = 0; s < 256; s++)
        acc = fmaf(ws[s], e[(size_t)(s0 + s) * ADIM + a], acc);
    g_ctx_part[blockIdx.y][a] = acc;

    __threadfence();
    if (threadIdx.x == 0) {
        int c = atomicAdd(&g_ctr_c, 1);
        is_last = (c == (int)(gridDim.x * gridDim.y) - 1);
        if (is_last) g_ctr_c = 0;
    }
    __syncthreads();
    if (!is_last) return;
    for (int i = threadIdx.x; i < ADIM; i += 256) {
        g_merge[i] = g_h[pnew][i];
        float cc = 0.f;
#pragma unroll
        for (int p = 0; p < 8; p++) cc += g_ctx_part[p][i];
        g_merge[HDIM + i] = cc;
    }
}

// bf16 vocab GEMV with exact bound; last block: vectorized candidate scan + exact fp32 rescore
__global__ void k_vocab(const float* __restrict__ Wout, const float* __restrict__ bout,
                        float* __restrict__ out, int t) {
    __shared__ __align__(16) float ms[MERGED];
    __shared__ float red[16];
    __shared__ int is_last;
    ((float4*)ms)[threadIdx.x] = ((const float4*)g_merge)[threadIdx.x];
    __syncthreads();
    int w = threadIdx.x >> 5, lane = threadIdx.x & 31;
    int v = blockIdx.x * 16 + w;
    if (v < VDIM) {
        const uint2* r2 = (const uint2*)(g_wbf + (size_t)v * MERGED);
        const float4* m4 = (const float4*)ms;
        float acc = 0.f, ab = 0.f;
#pragma unroll
        for (int i = 0; i < 16; i++) {
            uint2 u = __ldcs(r2 + lane + 32 * i);
            float4 m = m4[lane + 32 * i];
            float2 f0 = __bfloat1622float2(*(__nv_bfloat162*)&u.x);
            float2 f1 = __bfloat1622float2(*(__nv_bfloat162*)&u.y);
            acc = fmaf(f0.x, m.x, acc); ab = fmaf(fabsf(f0.x), fabsf(m.x), ab);
            acc = fmaf(f0.y, m.y, acc); ab = fmaf(fabsf(f0.y), fabsf(m.y), ab);
            acc = fmaf(f1.x, m.z, acc); ab = fmaf(fabsf(f1.x), fabsf(m.z), ab);
            acc = fmaf(f1.y, m.w, acc); ab = fmaf(fabsf(f1.y), fabsf(m.w), ab);
        }
        acc = warp_sum(acc);
        ab = warp_sum(ab);
        if (lane == 0) {
            float A = acc + bout[v];
            float B = fmaf(ab, 0.00390625f, 1e-4f);   // bf16 half-ulp bound + fp32-acc slack
            g_ub[v] = A + B;
            atomicMax(&g_M, enc_f(A - B));
        }
    }

    // ---- last block: candidate scan (vectorized, sync-free loop) + exact rescore ----
    __threadfence();
    if (threadIdx.x == 0) {
        int c = atomicAdd(&g_ctr_v, 1);
        is_last = (c == (int)gridDim.x - 1);
        if (is_last) g_ctr_v = 0;
    }
    __syncthreads();
    if (!is_last) return;

    __shared__ int s_cand[64];
    __shared__ int s_n;
    __shared__ float s_bl;
    __shared__ int s_bi;
    if (threadIdx.x == 0) { s_n = 0; s_bl = -3.4e38f; s_bi = 0; }
    __syncthreads();
    float thr = dec_f(g_M);
    const float4* ub4 = (const float4*)g_ub;
    for (int i = threadIdx.x; i < VPAD / 4; i += 512) {
        float4 u = ub4[i];
        if (u.x >= thr) { int p = atomicAdd(&s_n, 1); if (p < 64) s_cand[p] = 4 * i; }
        if (u.y >= thr) { int p = atomicAdd(&s_n, 1); if (p < 64) s_cand[p] = 4 * i + 1; }
        if (u.z >= thr) { int p = atomicAdd(&s_n, 1); if (p < 64) s_cand[p] = 4 * i + 2; }
        if (u.w >= thr) { int p = atomicAdd(&s_n, 1); if (p < 64) s_cand[p] = 4 * i + 3; }
    }
    __syncthreads();
    int n = min(s_n, 64);
    for (int c = 0; c < n; c++) {
        int vv = s_cand[c];
        const float4* r4 = (const float4*)(Wout + (size_t)vv * MERGED);
        float4 rr = __ldg(r4 + threadIdx.x);
        float4 mm = ((float4*)ms)[threadIdx.x];
        float a = fmaf(rr.x, mm.x, fmaf(rr.y, mm.y, fmaf(rr.z, mm.z, rr.w * mm.w)));
        a = warp_sum(a);
        if (lane == 0) red[w] = a;
        __syncthreads();
        if (threadIdx.x == 0) {
            float L = 0.f;
#pragma unroll
            for (int k = 0; k < 16; k++) L += red[k];
            L += bout[vv];
            if (L > s_bl || (L == s_bl && vv < s_bi)) { s_bl = L; s_bi = vv; }
        }
        __syncthreads();
    }
    if (threadIdx.x == 0) {
        g_word = s_bi;
        out[t] = (float)s_bi;
        g_M = 0u;   // reset for next step
    }
}

// ---------------- launch ----------------
extern "C" void kernel_launch(void* const* d_in, const int* in_sizes, int n_in,
                              void* d_out, int out_size) {
    const float* hidden     = (const float*)d_in[0];
    const float* embeddings = (const float*)d_in[1];
    const float* emb_table  = (const float*)d_in[2];
    const float* W_ih       = (const float*)d_in[3];
    const float* W_hh       = (const float*)d_in[4];
    const float* b_ih       = (const float*)d_in[5];
    const float* b_hh       = (const float*)d_in[6];
    const float* W_e        = (const float*)d_in[7];
    const float* W_q        = (const float*)d_in[8];
    const float* b_a        = (const float*)d_in[9];
    const float* v_a        = (const float*)d_in[10];
    const float* W_out      = (const float*)d_in[11];
    const float* b_out      = (const float*)d_in[12];
    float* out = (float*)d_out;

    k_init<<<1, 256>>>(hidden);
    {
        size_t n8 = (size_t)VDIM * MERGED / 8;
        int blocks = (int)((n8 + 511) / 512);
        k_quant<<<blocks, 512>>>(W_out);
    }
    k_eproj<<<dim3(SDIM / 32, ADIM / 32), dim3(32, 32)>>>(embeddings, W_e, b_a);

    for (int t = 0; t < NBOUND; t++) {
        int pold = t & 1;
        int pnew = pold ^ 1;
        k_gru<<<512, 384>>>(emb_table, W_ih, W_hh, b_ih, b_hh, pold);
        k_q<<<1024, 128>>>(W_q, pnew);
        k_s<<<256, 256>>>(v_a, out, t);
        k_ctx<<<dim3(4, 8), 256>>>(embeddings, pnew);
        k_vocab<<<(VDIM + 15) / 16, 512>>>(W_out, b_out, out, t);
    }
}

// round 4
// speedup vs baseline: 1.5652x; 1.1940x over previous
#include <cuda_runtime.h>
#include <cuda_bf16.h>
#include <cstdint>

#define HDIM 1024
#define SDIM 2048
#define VDIM 50257
#define NBOUND 25
#define MERGED 2048
#define NBLK 444           // 148 SMs x 3 co-resident blocks (guaranteed by launch_bounds)
#define NTHR 512
#define NWTOT (NBLK * 16)  // total warps = 7104

// ---------------- device scratch ----------------
__device__ __align__(16) float g_h[2][HDIM];
__device__ __align__(16) float g_q[HDIM];
__device__ __align__(16) float g_s[SDIM];
__device__ __align__(16) float g_ctx_part[8][HDIM];
__device__ __align__(16) float g_eproj[(size_t)SDIM * HDIM];          // 8 MB
__device__ __align__(16) __nv_bfloat16 g_wbf[(size_t)VDIM * MERGED];  // 206 MB
__device__ __align__(16) float g_ub[VDIM];
__device__ unsigned g_M[2];
__device__ unsigned long long g_best[2];
__device__ unsigned g_bar_count;
__device__ unsigned g_bar_phase;

// ---------------- helpers ----------------
__device__ __forceinline__ float warp_sum(float v) {
#pragma unroll
    for (int o = 16; o; o >>= 1) v += __shfl_xor_sync(0xffffffffu, v, o);
    return v;
}
__device__ __forceinline__ unsigned enc_f(float f) {
    unsigned b = __float_as_uint(f);
    return (b & 0x80000000u) ? ~b : (b | 0x80000000u);
}
__device__ __forceinline__ float dec_f(unsigned u) {
    unsigned b = (u & 0x80000000u) ? (u ^ 0x80000000u) : ~u;
    return __uint_as_float(b);
}
__device__ __forceinline__ float exp2_fast(float y) {
    y = fminf(fmaxf(y, -60.f), 60.f);
    float n = rintf(y);
    float f = y - n;
    float p = 1.5403530e-4f;
    p = fmaf(p, f, 1.3333558e-3f);
    p = fmaf(p, f, 9.6181291e-3f);
    p = fmaf(p, f, 5.5504109e-2f);
    p = fmaf(p, f, 2.4022651e-1f);
    p = fmaf(p, f, 6.9314718e-1f);
    p = fmaf(p, f, 1.0f);
    return __int_as_float(((int)n + 127) << 23) * p;
}
__device__ __forceinline__ float tanh_fast(float x) {
    float e = exp2_fast(x * 2.885390081777927f);
    return 1.f - 2.f / (e + 1.f);
}
__device__ __forceinline__ float sigmoid_fast(float x) {
    float e = exp2_fast(-1.4426950408889634f * x);
    return 1.f / (1.f + e);
}

// grid-wide sense barrier; monotone phase, wrap-safe compare, replay-safe (relative target)
__device__ __forceinline__ void gsync(unsigned& tgt) {
    __syncthreads();
    if (threadIdx.x == 0) {
        __threadfence();
        unsigned v = atomicAdd(&g_bar_count, 1u);
        if (v == NBLK - 1) {
            g_bar_count = 0;   // safe: nobody re-arrives until phase release below
            asm volatile("st.release.gpu.u32 [%0], %1;" :: "l"(&g_bar_phase), "r"(tgt) : "memory");
        } else {
            unsigned p;
            do {
                asm volatile("ld.acquire.gpu.u32 %0, [%1];" : "=r"(p) : "l"(&g_bar_phase) : "memory");
            } while ((int)(p - tgt) < 0);
        }
    }
    __syncthreads();
    tgt++;
}

// ---------------- the persistent mega-kernel ----------------
__global__ __launch_bounds__(NTHR, 3) void k_mega(
    const float* __restrict__ hidden, const float* __restrict__ emb,
    const float* __restrict__ emb_table,
    const float* __restrict__ W_ih, const float* __restrict__ W_hh,
    const float* __restrict__ b_ih, const float* __restrict__ b_hh,
    const float* __restrict__ We, const float* __restrict__ Wq,
    const float* __restrict__ ba, const float* __restrict__ va,
    const float* __restrict__ Wout, const float* __restrict__ bout,
    float* __restrict__ out)
{
    __shared__ __align__(16) float s_As[128 * 36];   // eproj A tile; reused as ms[2048] & sred
    __shared__ float s_Bs[64 * 33];                  // eproj B tile
    __shared__ float s_red[16];
    __shared__ int s_cand[32];
    __shared__ int s_cnt;
    __shared__ int s_word;

    const int tid = threadIdx.x;
    const int blk = blockIdx.x;
    const int w = tid >> 5, lane = tid & 31;
    const int gw = blk * 16 + w;

    // replay-safe barrier base (quiescent value; every block reads before any arrival)
    unsigned tgt = *((volatile unsigned*)&g_bar_phase) + 1;

    // ---------- phase 0: init + (eproj || quant) ----------
    if (blk == 0 && tid < 2) { g_M[tid] = 0u; g_best[tid] = 0ull; }
    if (blk == 1) {
        for (int i = tid; i < HDIM; i += NTHR) g_h[0][i] = hidden[i];
    }

    if (blk < 256) {
        // eproj tile: 128(s) x 64(a), 4x4 outputs/thread
        const int ts0 = (blk >> 4) * 128;
        const int ta0 = (blk & 15) * 64;
        const int ts = tid >> 4;    // 0..31
        const int ta = tid & 15;    // 0..15
        float acc[4][4];
#pragma unroll
        for (int i = 0; i < 4; i++)
#pragma unroll
            for (int j = 0; j < 4; j++) acc[i][j] = 0.f;

        for (int kt = 0; kt < 1024; kt += 32) {
#pragma unroll
            for (int r = 0; r < 8; r++) {
                int e0 = tid + NTHR * r;            // 0..4095
                int si = e0 >> 5, kk = e0 & 31;
                s_As[si * 36 + kk] = emb[(size_t)(ts0 + si) * 1024 + kt + kk];
            }
#pragma unroll
            for (int r = 0; r < 4; r++) {
                int e0 = tid + NTHR * r;            // 0..2047
                int ai = e0 >> 5, kk = e0 & 31;
                s_Bs[ai * 33 + kk] = We[(size_t)(ta0 + ai) * 1024 + kt + kk];
            }
            __syncthreads();
#pragma unroll
            for (int k = 0; k < 32; k++) {
                float a0 = s_As[ts * 36 + k];
                float a1 = s_As[(ts + 32) * 36 + k];
                float a2 = s_As[(ts + 64) * 36 + k];
                float a3 = s_As[(ts + 96) * 36 + k];
                float b0 = s_Bs[(ta * 4 + 0) * 33 + k];
                float b1 = s_Bs[(ta * 4 + 1) * 33 + k];
                float b2 = s_Bs[(ta * 4 + 2) * 33 + k];
                float b3 = s_Bs[(ta * 4 + 3) * 33 + k];
                acc[0][0] = fmaf(a0, b0, acc[0][0]); acc[0][1] = fmaf(a0, b1, acc[0][1]);
                acc[0][2] = fmaf(a0, b2, acc[0][2]); acc[0][3] = fmaf(a0, b3, acc[0][3]);
                acc[1][0] = fmaf(a1, b0, acc[1][0]); acc[1][1] = fmaf(a1, b1, acc[1][1]);
                acc[1][2] = fmaf(a1, b2, acc[1][2]); acc[1][3] = fmaf(a1, b3, acc[1][3]);
                acc[2][0] = fmaf(a2, b0, acc[2][0]); acc[2][1] = fmaf(a2, b1, acc[2][1]);
                acc[2][2] = fmaf(a2, b2, acc[2][2]); acc[2][3] = fmaf(a2, b3, acc[2][3]);
                acc[3][0] = fmaf(a3, b0, acc[3][0]); acc[3][1] = fmaf(a3, b1, acc[3][1]);
                acc[3][2] = fmaf(a3, b2, acc[3][2]); acc[3][3] = fmaf(a3, b3, acc[3][3]);
            }
            __syncthreads();
        }
        float4 bb = __ldg((const float4*)(ba + ta0) + ta);
#pragma unroll
        for (int i = 0; i < 4; i++) {
            float4 o = make_float4(acc[i][0] + bb.x, acc[i][1] + bb.y,
                                   acc[i][2] + bb.z, acc[i][3] + bb.w);
            *(float4*)&g_eproj[(size_t)(ts0 + ts + 32 * i) * 1024 + ta0 + ta * 4] = o;
        }
    } else {
        // quant: fp32 W_out -> bf16, streaming both directions
        const size_t n8 = (size_t)VDIM * MERGED / 8;
        for (size_t idx = (size_t)(blk - 256) * NTHR + tid; idx < n8;
             idx += (size_t)(NBLK - 256) * NTHR) {
            const float4* p = (const float4*)Wout + idx * 2;
            float4 a = __ldcs(p);
            float4 b = __ldcs(p + 1);
            uint4 o;
            *(__nv_bfloat162*)&o.x = __nv_bfloat162(__float2bfloat16(a.x), __float2bfloat16(a.y));
            *(__nv_bfloat162*)&o.y = __nv_bfloat162(__float2bfloat16(a.z), __float2bfloat16(a.w));
            *(__nv_bfloat162*)&o.z = __nv_bfloat162(__float2bfloat16(b.x), __float2bfloat16(b.y));
            *(__nv_bfloat162*)&o.w = __nv_bfloat162(__float2bfloat16(b.z), __float2bfloat16(b.w));
            __stcs((uint4*)g_wbf + idx, o);
        }
    }
    gsync(tgt);

    // ---------- decode loop ----------
    int word = 1;  // SOS
    for (int t = 0; t < NBOUND; t++) {
        const int par = t & 1;
        const int pold = par, pnew = par ^ 1;

        // ---- GRU: one warp per hidden row j, 6 accumulators ----
        {
            int j = w * NBLK + blk;
            if (w < 3 && j < 1024) {
                const float4* xv = (const float4*)(emb_table + (size_t)word * 1024);
                const float4* hv = (const float4*)g_h[pold];
                const float4* m0 = (const float4*)(W_ih + (size_t)j * 1024);
                const float4* m1 = (const float4*)(W_ih + (size_t)(1024 + j) * 1024);
                const float4* m2 = (const float4*)(W_ih + (size_t)(2048 + j) * 1024);
                const float4* m3 = (const float4*)(W_hh + (size_t)j * 1024);
                const float4* m4p = (const float4*)(W_hh + (size_t)(1024 + j) * 1024);
                const float4* m5 = (const float4*)(W_hh + (size_t)(2048 + j) * 1024);
                float a0 = 0, a1 = 0, a2 = 0, a3 = 0, a4 = 0, a5 = 0;
#pragma unroll 4
                for (int i = 0; i < 8; i++) {
                    int k = lane + 32 * i;
                    float4 x = __ldg(xv + k);
                    float4 h = __ldcg(hv + k);
                    float4 m;
                    m = __ldg(m0 + k); a0 = fmaf(m.x, x.x, a0); a0 = fmaf(m.y, x.y, a0); a0 = fmaf(m.z, x.z, a0); a0 = fmaf(m.w, x.w, a0);
                    m = __ldg(m1 + k); a1 = fmaf(m.x, x.x, a1); a1 = fmaf(m.y, x.y, a1); a1 = fmaf(m.z, x.z, a1); a1 = fmaf(m.w, x.w, a1);
                    m = __ldg(m2 + k); a2 = fmaf(m.x, x.x, a2); a2 = fmaf(m.y, x.y, a2); a2 = fmaf(m.z, x.z, a2); a2 = fmaf(m.w, x.w, a2);
                    m = __ldg(m3 + k); a3 = fmaf(m.x, h.x, a3); a3 = fmaf(m.y, h.y, a3); a3 = fmaf(m.z, h.z, a3); a3 = fmaf(m.w, h.w, a3);
                    m = __ldg(m4p + k); a4 = fmaf(m.x, h.x, a4); a4 = fmaf(m.y, h.y, a4); a4 = fmaf(m.z, h.z, a4); a4 = fmaf(m.w, h.w, a4);
                    m = __ldg(m5 + k); a5 = fmaf(m.x, h.x, a5); a5 = fmaf(m.y, h.y, a5); a5 = fmaf(m.z, h.z, a5); a5 = fmaf(m.w, h.w, a5);
                }
                a0 = warp_sum(a0); a1 = warp_sum(a1); a2 = warp_sum(a2);
                a3 = warp_sum(a3); a4 = warp_sum(a4); a5 = warp_sum(a5);
                if (lane == 0) {
                    float gr = a0 + __ldg(&b_ih[j]);
                    float gz = a1 + __ldg(&b_ih[1024 + j]);
                    float gn = a2 + __ldg(&b_ih[2048 + j]);
                    float hr = a3 + __ldg(&b_hh[j]);
                    float hz = a4 + __ldg(&b_hh[1024 + j]);
                    float hn = a5 + __ldg(&b_hh[2048 + j]);
                    float r = sigmoid_fast(gr + hr);
                    float z = sigmoid_fast(gz + hz);
                    float n = tanh_fast(gn + r * hn);
                    float hold = __ldcg(&g_h[pold][j]);
                    __stcg(&g_h[pnew][j], (1.f - z) * n + z * hold);
                }
            }
        }
        gsync(tgt);
        // reset previous parity's argmax state (read completed before B1 arrival)
        if (blk == 0 && tid == 0) {
            atomicExch(&g_M[par ^ 1], 0u);
            atomicExch(&g_best[par ^ 1], 0ull);
        }

        // ---- q[a] = h_new . Wq[a,:] ----
        {
            int a = w * NBLK + blk;
            if (w < 3 && a < 1024) {
                const float4* mq = (const float4*)(Wq + (size_t)a * 1024);
                const float4* hv = (const float4*)g_h[pnew];
                float acc = 0.f;
#pragma unroll
                for (int i = 0; i < 8; i++) {
                    int k = lane + 32 * i;
                    float4 m = __ldg(mq + k);
                    float4 h = __ldcg(hv + k);
                    acc = fmaf(m.x, h.x, acc); acc = fmaf(m.y, h.y, acc);
                    acc = fmaf(m.z, h.z, acc); acc = fmaf(m.w, h.w, acc);
                }
                acc = warp_sum(acc);
                if (lane == 0) __stcg(&g_q[a], acc);
            }
        }
        gsync(tgt);

        // ---- s[j] = sum_a tanh(eproj[j,a] + q[a]) * v_a[a] ----
        {
            int j = w * NBLK + blk;
            if (w < 5 && j < 2048) {
                const float4* ep = (const float4*)(g_eproj + (size_t)j * 1024);
                const float4* qv = (const float4*)g_q;
                const float4* vv = (const float4*)va;
                float acc = 0.f;
#pragma unroll 4
                for (int i = 0; i < 8; i++) {
                    int k = lane + 32 * i;
                    float4 e4 = __ldg(ep + k);
                    float4 q4 = __ldcg(qv + k);
                    float4 v4 = __ldg(vv + k);
                    acc = fmaf(tanh_fast(e4.x + q4.x), v4.x, acc);
                    acc = fmaf(tanh_fast(e4.y + q4.y), v4.y, acc);
                    acc = fmaf(tanh_fast(e4.z + q4.z), v4.z, acc);
                    acc = fmaf(tanh_fast(e4.w + q4.w), v4.w, acc);
                }
                acc = warp_sum(acc);
                if (lane == 0) __stcg(&g_s[j], acc);
            }
        }
        gsync(tgt);

        // ---- softmax (local stats) + ctx partials + weights output ----
        if (blk < 128) {
            // local softmax stats over all 2048 scores
            float v4[4];
            float lm = -3.4e38f;
#pragma unroll
            for (int r = 0; r < 4; r++) {
                v4[r] = __ldcg(&g_s[tid + 512 * r]);
                lm = fmaxf(lm, v4[r]);
            }
#pragma unroll
            for (int o = 16; o; o >>= 1) lm = fmaxf(lm, __shfl_xor_sync(0xffffffffu, lm, o));
            if (lane == 0) s_red[w] = lm;
            __syncthreads();
            float m = s_red[0];
#pragma unroll
            for (int k = 1; k < 16; k++) m = fmaxf(m, s_red[k]);
            __syncthreads();
            float ls = 0.f;
#pragma unroll
            for (int r = 0; r < 4; r++) ls += expf(v4[r] - m);
            ls = warp_sum(ls);
            if (lane == 0) s_red[w] = ls;
            __syncthreads();
            float tot = s_red[0];
#pragma unroll
            for (int k = 1; k < 16; k++) tot += s_red[k];
            float inv = 1.f / tot;

            if (blk == 0) {
                size_t base = (size_t)NBOUND + (size_t)t * SDIM;
#pragma unroll
                for (int r = 0; r < 4; r++)
                    out[base + tid + 512 * r] = expf(v4[r] - m) * inv;
            }

            // ctx partial: s-chunk of 256, a-chunk of 64
            int sc = blk >> 4;        // 0..7
            int ac = blk & 15;        // 0..15
            int a0 = ac * 64;
            int g = tid >> 6, al = tid & 63;
            float acc = 0.f;
            int sb = sc * 256 + g * 32;
            for (int ss = 0; ss < 32; ss++) {
                int s = sb + ss;
                float wv = expf(__ldcg(&g_s[s]) - m) * inv;
                acc = fmaf(wv, __ldg(&emb[(size_t)s * 1024 + a0 + al]), acc);
            }
            float* sred = s_As;
            sred[g * 64 + al] = acc;
            __syncthreads();
            if (tid < 64) {
                float c = 0.f;
#pragma unroll
                for (int gg = 0; gg < 8; gg++) c += sred[gg * 64 + tid];
                __stcg(&g_ctx_part[sc][a0 + tid], c);
            }
        }
        gsync(tgt);

        // ---- vocab: bf16 GEMV + bound; each block builds merge in smem ----
        float* ms = s_As;
        for (int i = tid; i < 1024; i += NTHR) ms[i] = __ldcg(&g_h[pnew][i]);
        for (int i = tid; i < 1024; i += NTHR) {
            float c = 0.f;
#pragma unroll
            for (int p = 0; p < 8; p++) c += __ldcg(&g_ctx_part[p][i]);
            ms[1024 + i] = c;
        }
        __syncthreads();
        const float4* m4 = (const float4*)ms;
        for (int v = gw; v < VDIM; v += NWTOT) {
            const unsigned long long* r8 =
                (const unsigned long long*)(g_wbf + (size_t)v * MERGED);
            float acc = 0.f, ab = 0.f;
#pragma unroll 8
            for (int i = 0; i < 16; i++) {
                unsigned long long u = __ldcs(r8 + lane + 32 * i);
                float4 mm = m4[lane + 32 * i];
                unsigned lo = (unsigned)u, hi = (unsigned)(u >> 32);
                float2 f0 = __bfloat1622float2(*(__nv_bfloat162*)&lo);
                float2 f1 = __bfloat1622float2(*(__nv_bfloat162*)&hi);
                acc = fmaf(f0.x, mm.x, acc); ab = fmaf(fabsf(f0.x), fabsf(mm.x), ab);
                acc = fmaf(f0.y, mm.y, acc); ab = fmaf(fabsf(f0.y), fabsf(mm.y), ab);
                acc = fmaf(f1.x, mm.z, acc); ab = fmaf(fabsf(f1.x), fabsf(mm.z), ab);
                acc = fmaf(f1.y, mm.w, acc); ab = fmaf(fabsf(f1.y), fabsf(mm.w), ab);
            }
            acc = warp_sum(acc);
            ab = warp_sum(ab);
            if (lane == 0) {
                float A = acc + __ldg(&bout[v]);
                float B = fmaf(ab, 0.00390625f, 1e-4f);
                __stcg(&g_ub[v], A + B);
                atomicMax(&g_M[par], enc_f(A - B));
            }
        }
        gsync(tgt);

        // ---- scan + exact fp32 rescore of margin candidates ----
        if (tid == 0) s_cnt = 0;
        __syncthreads();
        {
            float thr = dec_f(__ldcg(&g_M[par]));
            int i = blk * NTHR + tid;
            if (i < VDIM && __ldcg(&g_ub[i]) >= thr) {
                int p = atomicAdd(&s_cnt, 1);
                if (p < 32) s_cand[p] = i;
            }
        }
        __syncthreads();
        int nc = min(s_cnt, 32);
        for (int c = 0; c < nc; c++) {
            int v = s_cand[c];
            float4 rr = __ldg((const float4*)(Wout + (size_t)v * MERGED) + tid);
            float4 mm = m4[tid];
            float a = fmaf(rr.x, mm.x, fmaf(rr.y, mm.y, fmaf(rr.z, mm.z, rr.w * mm.w)));
            a = warp_sum(a);
            if (lane == 0) s_red[w] = a;
            __syncthreads();
            if (tid == 0) {
                float L = 0.f;
#pragma unroll
                for (int k = 0; k < 16; k++) L += s_red[k];
                L += __ldg(&bout[v]);
                unsigned long long pk =
                    ((unsigned long long)enc_f(L) << 32) |
                    (unsigned long long)(0xFFFFFFFFu - (unsigned)v);
                atomicMax(&g_best[par], pk);
            }
            __syncthreads();
        }
        gsync(tgt);

        if (tid == 0) {
            unsigned long long pk = __ldcg(&g_best[par]);
            int wd = (int)(0xFFFFFFFFu - (unsigned)(pk & 0xFFFFFFFFull));
            s_word = wd;
            if (blk == 0) out[t] = (float)wd;
        }
        __syncthreads();
        word = s_word;
    }
}

// ---------------- launch ----------------
extern "C" void kernel_launch(void* const* d_in, const int* in_sizes, int n_in,
                              void* d_out, int out_size) {
    const float* hidden     = (const float*)d_in[0];
    const float* embeddings = (const float*)d_in[1];
    const float* emb_table  = (const float*)d_in[2];
    const float* W_ih       = (const float*)d_in[3];
    const float* W_hh       = (const float*)d_in[4];
    const float* b_ih       = (const float*)d_in[5];
    const float* b_hh       = (const float*)d_in[6];
    const float* W_e        = (const float*)d_in[7];
    const float* W_q        = (const float*)d_in[8];
    const float* b_a        = (const float*)d_in[9];
    const float* v_a        = (const float*)d_in[10];
    const float* W_out      = (const float*)d_in[11];
    const float* b_out      = (const float*)d_in[12];
    float* out = (float*)d_out;

    k_mega<<<NBLK, NTHR>>>(hidden, embeddings, emb_table, W_ih, W_hh, b_ih, b_hh,
                           W_e, W_q, b_a, v_a, W_out, b_out, out);
}